// round 7
// baseline (speedup 1.0000x reference)
#include <cuda_runtime.h>
#include <cuda_fp16.h>
#include <cstdint>

// DynamicFeedForward:
//   input_value [4,2048,512] f32
//   mask_tensor [4,2048,32] i32
//   weight      [50000,512] f32
//   bias        [50000]     f32
// out[b,s,m] = relu( dot(input[b,s,:], weight[mask[b,s,m],:]) + bias[mask[b,s,m]] )
//
// Phase 1: repack W -> fp16 table (__ldcs streams W; table write-back stays in L2).
// Phase 2: gather+dot at the LTS cap; software-pipelined; cheap 4-way warp reduce.

static constexpr int HIDDEN   = 512;
static constexpr int NCAND    = 32;
static constexpr int NROWS    = 50000;
static constexpr int THREADS  = 256;   // 8 warps = 8 tokens per CTA

__device__ __align__(16) __half g_wh[(size_t)NROWS * HIDDEN];   // 51.2 MB scratch

// ---------------- conversion: fp32 W -> fp16 table (R4-exact) ----------------
__global__ __launch_bounds__(256)
void convert_kernel(const float* __restrict__ W, int n_vec8)
{
    int i = blockIdx.x * blockDim.x + threadIdx.x;   // one thread = 8 floats
    if (i >= n_vec8) return;
    const float4* w4 = reinterpret_cast<const float4*>(W) + (size_t)i * 2;
    float4 f0 = __ldcs(w4 + 0);     // evict-first: don't let W evict the fp16 table
    float4 f1 = __ldcs(w4 + 1);
    __half2 h[4];
    h[0] = __floats2half2_rn(f0.x, f0.y);
    h[1] = __floats2half2_rn(f0.z, f0.w);
    h[2] = __floats2half2_rn(f1.x, f1.y);
    h[3] = __floats2half2_rn(f1.z, f1.w);
    reinterpret_cast<uint4*>(g_wh)[i] = *reinterpret_cast<uint4*>(h);   // write-back: table stays in L2
}

// ---------------- gather / dot ----------------
__device__ __forceinline__ float dot8(const uint4 v, const float4 aA, const float4 aB)
{
    const __half2* h = reinterpret_cast<const __half2*>(&v);
    float s = 0.f;
    float2 f;
    f = __half22float2(h[0]); s = fmaf(aA.x, f.x, s); s = fmaf(aA.y, f.y, s);
    f = __half22float2(h[1]); s = fmaf(aA.z, f.x, s); s = fmaf(aA.w, f.y, s);
    f = __half22float2(h[2]); s = fmaf(aB.x, f.x, s); s = fmaf(aB.y, f.y, s);
    f = __half22float2(h[3]); s = fmaf(aB.z, f.x, s); s = fmaf(aB.w, f.y, s);
    return s;
}

__global__ __launch_bounds__(THREADS)
void dff_kernel(const float* __restrict__ inp,
                const int* __restrict__ mask,
                const float* __restrict__ B,
                float* __restrict__ out,
                int n_tokens)
{
    const int lane  = threadIdx.x & 31;
    const int token = blockIdx.x * 8 + (threadIdx.x >> 5);
    if (token >= n_tokens) return;

    // Stage this lane's 16 input floats: [8l,8l+8) and [256+8l,256+8l+8).
    const float* in_row = inp + (size_t)token * HIDDEN;
    const float4 a0 = *reinterpret_cast<const float4*>(in_row + 8 * lane + 0);
    const float4 a1 = *reinterpret_cast<const float4*>(in_row + 8 * lane + 4);
    const float4 a2 = *reinterpret_cast<const float4*>(in_row + 256 + 8 * lane + 0);
    const float4 a3 = *reinterpret_cast<const float4*>(in_row + 256 + 8 * lane + 4);

    // Lane l owns candidate l's index and bias.
    const int midx   = mask[(size_t)token * NCAND + lane];
    const float bval = __ldg(B + midx);

    const bool hi8  = (lane & 8)  != 0;
    const bool hi16 = (lane & 16) != 0;
    // Source lane that holds candidate (lane&3) after the fold: bit3 = k>>1, bit4 = k&1.
    const int k_mine   = lane & 3;
    const int src_lane = ((k_mine >> 1) << 3) | ((k_mine & 1) << 4);
    const int my_group = lane >> 2;   // which 4-candidate group produces my output

    // Prologue: issue group 0's 8 loads.
    uint4 v0[4], v1[4];
    #pragma unroll
    for (int k = 0; k < 4; k++) {
        const int idx = __shfl_sync(0xFFFFFFFFu, midx, k);
        const __half* w = g_wh + (size_t)idx * HIDDEN;
        v0[k] = __ldcg(reinterpret_cast<const uint4*>(w + 8 * lane));
        v1[k] = __ldcg(reinterpret_cast<const uint4*>(w + 256 + 8 * lane));
    }

    float res = 0.f;

    #pragma unroll
    for (int c = 0; c < NCAND; c += 4) {
        // Consume current group's data.
        float s0 = dot8(v0[0], a0, a1) + dot8(v1[0], a2, a3);
        float s1 = dot8(v0[1], a0, a1) + dot8(v1[1], a2, a3);
        float s2 = dot8(v0[2], a0, a1) + dot8(v1[2], a2, a3);
        float s3 = dot8(v0[3], a0, a1) + dot8(v1[3], a2, a3);

        // Prefetch next group's 8 loads BEFORE the reduce chain.
        if (c + 4 < NCAND) {
            #pragma unroll
            for (int k = 0; k < 4; k++) {
                const int idx = __shfl_sync(0xFFFFFFFFu, midx, c + 4 + k);
                const __half* w = g_wh + (size_t)idx * HIDDEN;
                v0[k] = __ldcg(reinterpret_cast<const uint4*>(w + 8 * lane));
                v1[k] = __ldcg(reinterpret_cast<const uint4*>(w + 256 + 8 * lane));
            }
        }

        // Fold 4 partials -> 1 per lane.
        // Stage 1 (xor 8): bit3=0 lanes keep candidates {0,1}, bit3=1 keep {2,3}.
        float q0 = __shfl_xor_sync(0xFFFFFFFFu, hi8 ? s0 : s2, 8);
        float q1 = __shfl_xor_sync(0xFFFFFFFFu, hi8 ? s1 : s3, 8);
        float u0 = (hi8 ? s2 : s0) + q0;
        float u1 = (hi8 ? s3 : s1) + q1;
        // Stage 2 (xor 16): bit4=0 keeps u0's candidate, bit4=1 keeps u1's.
        float q2 = __shfl_xor_sync(0xFFFFFFFFu, hi16 ? u0 : u1, 16);
        float v  = (hi16 ? u1 : u0) + q2;
        // v = candidate c + 2*bit3 + bit4, summed over {l, l^8, l^16, l^24}.
        // Stage 3: finish over bits 0..2.
        v += __shfl_xor_sync(0xFFFFFFFFu, v, 1);
        v += __shfl_xor_sync(0xFFFFFFFFu, v, 2);
        v += __shfl_xor_sync(0xFFFFFFFFu, v, 4);

        // Route candidate (lane) to its output lane.
        float r = __shfl_sync(0xFFFFFFFFu, v, src_lane);
        if (my_group == (c >> 2)) res = r;
    }

    // Coalesced 128B store: lane l writes candidate l.
    out[(size_t)token * NCAND + lane] = fmaxf(res + bval, 0.0f);
}

extern "C" void kernel_launch(void* const* d_in, const int* in_sizes, int n_in,
                              void* d_out, int out_size)
{
    const float* inp  = (const float*)d_in[0];
    const int*   mask = (const int*)d_in[1];
    const float* W    = (const float*)d_in[2];
    const float* B    = (const float*)d_in[3];
    float* out = (float*)d_out;

    const int n_tokens = in_sizes[0] / HIDDEN;           // 8192
    const int n_vec8   = NROWS * HIDDEN / 8;             // 3.2M
    const int conv_blk = (n_vec8 + 255) / 256;

    convert_kernel<<<conv_blk, 256>>>(W, n_vec8);
    dff_kernel<<<(n_tokens + 7) / 8, THREADS>>>(inp, mask, B, out, n_tokens);
}